// round 4
// baseline (speedup 1.0000x reference)
#include <cuda_runtime.h>
#include <math.h>

#define B_    32
#define INC_  10
#define LIN_  16384
#define CH_   20
#define NPOLY 12
#define MM_   6
#define NB_   4
// lengths: l0=16434, each block shrinks by 12 -> 16422,16410,16398,16386

#define BUFN 10520000  // >= 32*20*16434

__device__ float g_xa[BUFN];
__device__ float g_xb[BUFN];
__device__ float g_y1[BUFN];
__device__ float g_y2[BUFN];

// Branchless gelu: Abramowitz-Stegun 7.1.26 erf approx (|abs err| < 1.5e-7)
__device__ __forceinline__ float gelu_f(float x) {
    float z = 0.7071067811865476f * x;
    float s = fabsf(z);
    float t = __fdividef(1.0f, fmaf(0.3275911f, s, 1.0f));
    float p = fmaf(fmaf(fmaf(fmaf(1.061405429f, t, -1.453152027f),
                             t, 1.421413741f), t, -0.284496736f), t, 0.254829592f) * t;
    float e = __expf(-s * s);
    float er = fmaf(-p, e, 1.0f);          // erf(|z|)
    er = copysignf(er, z);
    return 0.5f * x * (1.0f + er);
}

// ---------------------------------------------------------------------------
// First conv: input (B,10,16384) wrap-padded (25,27), conv3 -> (B,20,16434)
// ---------------------------------------------------------------------------
__global__ void __launch_bounds__(128) k_first(
    const float* __restrict__ in, const float* __restrict__ w,
    float* __restrict__ out, int lout)
{
    __shared__ float sw[CH_ * INC_ * 3];
    int tid = threadIdx.x;
    for (int i = tid; i < CH_ * INC_ * 3; i += blockDim.x) sw[i] = w[i];
    __syncthreads();

    int b = blockIdx.y;
    int t = blockIdx.x * blockDim.x + tid;
    if (t >= lout) return;

    int base = t - 25;
    int i0 = base;     if (i0 < 0) i0 += LIN_; else if (i0 >= LIN_) i0 -= LIN_;
    int i1 = base + 1; if (i1 < 0) i1 += LIN_; else if (i1 >= LIN_) i1 -= LIN_;
    int i2 = base + 2; if (i2 < 0) i2 += LIN_; else if (i2 >= LIN_) i2 -= LIN_;

    const float* inb = in + (size_t)b * INC_ * LIN_;
    float acc[CH_];
#pragma unroll
    for (int co = 0; co < CH_; co++) acc[co] = 0.f;
#pragma unroll
    for (int ci = 0; ci < INC_; ci++) {
        float v0 = inb[ci * LIN_ + i0];
        float v1 = inb[ci * LIN_ + i1];
        float v2 = inb[ci * LIN_ + i2];
#pragma unroll
        for (int co = 0; co < CH_; co++) {
            const float* wp = sw + (co * INC_ + ci) * 3;
            acc[co] = fmaf(wp[0], v0, fmaf(wp[1], v1, fmaf(wp[2], v2, acc[co])));
        }
    }
    float* ob = out + (size_t)b * CH_ * lout;
#pragma unroll
    for (int co = 0; co < CH_; co++) ob[co * lout + t] = acc[co];
}

// ---------------------------------------------------------------------------
// conv3 20->20 VALID, optional gelu. 4 warps x 5 co each; V=6 positions/thread.
// Weights hoisted to registers per-ci (15 LDS per 90 FMA).
// ---------------------------------------------------------------------------
#define NTC 192
#define XROW 200   // >= NTC+2

template <bool DO_GELU>
__global__ void __launch_bounds__(128) k_conv5(
    const float* __restrict__ x, const float* __restrict__ w,
    float* __restrict__ out, int lin)
{
    __shared__ float xs[CH_][XROW];
    __shared__ float sw[CH_ * CH_ * 3];

    int tid = threadIdx.x;
    int b = blockIdx.y;
    int T0 = blockIdx.x * NTC;
    int lout = lin - 2;

    for (int i = tid; i < CH_ * CH_ * 3; i += 128) sw[i] = w[i];
    for (int i = tid; i < CH_ * (NTC + 2); i += 128) {
        int ci = i / (NTC + 2), j = i % (NTC + 2);
        int gp = T0 + j;
        xs[ci][j] = (gp < lin) ? x[((size_t)b * CH_ + ci) * lin + gp] : 0.f;
    }
    __syncthreads();

    int wq = tid >> 5, lane = tid & 31;
    int cob = 5 * wq;

    float a[5][6];
#pragma unroll
    for (int cc = 0; cc < 5; cc++)
#pragma unroll
        for (int v = 0; v < 6; v++) a[cc][v] = 0.f;

#pragma unroll
    for (int ci = 0; ci < CH_; ci++) {
        float wr[15];
#pragma unroll
        for (int cc = 0; cc < 5; cc++)
#pragma unroll
            for (int k = 0; k < 3; k++)
                wr[cc * 3 + k] = sw[((cob + cc) * CH_ + ci) * 3 + k];
#pragma unroll
        for (int v = 0; v < 6; v++) {
            int j = lane + 32 * v;
            float x0 = xs[ci][j], x1 = xs[ci][j + 1], x2 = xs[ci][j + 2];
#pragma unroll
            for (int cc = 0; cc < 5; cc++)
                a[cc][v] = fmaf(wr[cc * 3], x0,
                           fmaf(wr[cc * 3 + 1], x1,
                           fmaf(wr[cc * 3 + 2], x2, a[cc][v])));
        }
    }
#pragma unroll
    for (int v = 0; v < 6; v++) {
        int t = T0 + lane + 32 * v;
        if (t < lout) {
#pragma unroll
            for (int cc = 0; cc < 5; cc++) {
                float u = a[cc][v];
                if (DO_GELU) u = gelu_f(u);
                out[((size_t)b * CH_ + cob + cc) * lout + t] = u;
            }
        }
    }
}

// ---------------------------------------------------------------------------
// Fused Legendre decompose + block-diag mix + overlap-add recon + residual + gelu.
// Flat mode-major axis q = mi*20+ci; group g mixes q in [6g,6g+6).
// Tile: NTO=192 outputs -> tau in [tau0, tau0+32] (33 values).
// ---------------------------------------------------------------------------
#define NTO 192
#define NTAU 33
#define XR 208   // >= 6*32+12 = 204

__global__ void __launch_bounds__(256) k_legrec(
    const float* __restrict__ x, const float* __restrict__ lm_g,
    const float* __restrict__ fd, const float* __restrict__ fr,
    const float* __restrict__ y2, float* __restrict__ out,
    int l, int lo)
{
    __shared__ float xs[CH_][XR];
    __shared__ float u[120][NTAU + 1];
    __shared__ float fd2[MM_ * NPOLY];
    __shared__ float sfr[MM_ * NPOLY];
    __shared__ float lm[CH_ * MM_ * MM_];

    int tid = threadIdx.x;
    int b = blockIdx.y;
    int T0 = blockIdx.x * NTO;
    int tau0 = T0 / 6;

    for (int i = tid; i < MM_ * NPOLY; i += 256) { fd2[i] = 0.5f * fd[i]; sfr[i] = fr[i]; }
    for (int i = tid; i < CH_ * MM_ * MM_; i += 256) lm[i] = lm_g[i];
    for (int i = tid; i < CH_ * 204; i += 256) {
        int ci = i / 204, j = i % 204;
        int gp = 6 * tau0 + j;
        xs[ci][j] = (gp < l) ? x[((size_t)b * CH_ + ci) * l + gp] : 0.f;
    }
    __syncthreads();

    // Stage 2: v (regs) -> u (smem). Tasks: (g, s), 20*33 = 660.
    for (int task = tid; task < CH_ * NTAU; task += 256) {
        int g = task % CH_;
        int s = task / CH_;
        float v[MM_];
#pragma unroll
        for (int i = 0; i < MM_; i++) {
            int q = 6 * g + i;
            int mi = q / CH_;
            int ci = q % CH_;
            float acc = 0.f;
#pragma unroll
            for (int k = 0; k < NPOLY; k++)
                acc = fmaf(fd2[mi * NPOLY + k], xs[ci][6 * s + k], acc);
            v[i] = acc;
        }
#pragma unroll
        for (int o = 0; o < MM_; o++) {
            float acc = 0.f;
#pragma unroll
            for (int i = 0; i < MM_; i++)
                acc = fmaf(lm[(g * MM_ + o) * MM_ + i], v[i], acc);
            u[6 * g + o][s] = acc;
        }
    }
    __syncthreads();

    // Stage 3: reconstruct + residual + gelu. Tasks: (co, tloc), 20*192.
    int l2row = lo + 8;
    for (int task = tid; task < CH_ * NTO; task += 256) {
        int co = task / NTO;
        int tloc = task % NTO;
        int t = T0 + tloc;
        if (t >= lo) continue;

        int pg = t + 6;
        int t0 = pg / 6;
        int k0 = pg - 6 * t0;
        int s = t0 - tau0;   // in [1, 32]

        float acc = 0.f;
#pragma unroll
        for (int mo = 0; mo < MM_; mo++) {
            int pp = mo * CH_ + co;
            acc = fmaf(u[pp][s],     sfr[mo * NPOLY + k0],     acc);
            acc = fmaf(u[pp][s - 1], sfr[mo * NPOLY + k0 + 6], acc);
        }
        float val = acc + y2[((size_t)b * CH_ + co) * l2row + t + 4];
        out[((size_t)b * CH_ + co) * lo + t] = gelu_f(val);
    }
}

// ---------------------------------------------------------------------------
// Final: out[b,t] = sum_o w_out[o] * gelu(sum_c w11[o,c]*x[b,c,t]), VT=2
// ---------------------------------------------------------------------------
__global__ void __launch_bounds__(128) k_final(
    const float* __restrict__ x, const float* __restrict__ w11,
    const float* __restrict__ w_out, float* __restrict__ out, int lin)
{
    __shared__ float sw[128 * CH_];
    __shared__ float so[128];
    int tid = threadIdx.x;
    for (int i = tid; i < 128 * CH_; i += blockDim.x) sw[i] = w11[i];
    if (tid < 128) so[tid] = w_out[tid];
    __syncthreads();

    int b = blockIdx.y;
    int t0 = (blockIdx.x * blockDim.x + tid) * 2;
    if (t0 >= LIN_) return;

    const float* xb = x + (size_t)b * CH_ * lin + t0;
    float xv0[CH_], xv1[CH_];
#pragma unroll
    for (int c = 0; c < CH_; c++) { xv0[c] = xb[c * lin]; xv1[c] = xb[c * lin + 1]; }

    float acc0 = 0.f, acc1 = 0.f;
#pragma unroll 4
    for (int o = 0; o < 128; o++) {
        float h0 = 0.f, h1 = 0.f;
#pragma unroll
        for (int c = 0; c < CH_; c++) {
            float wv = sw[o * CH_ + c];
            h0 = fmaf(wv, xv0[c], h0);
            h1 = fmaf(wv, xv1[c], h1);
        }
        float ov = so[o];
        acc0 = fmaf(ov, gelu_f(h0), acc0);
        acc1 = fmaf(ov, gelu_f(h1), acc1);
    }
    out[(size_t)b * LIN_ + t0] = acc0;
    out[(size_t)b * LIN_ + t0 + 1] = acc1;
}

// ---------------------------------------------------------------------------
extern "C" void kernel_launch(void* const* d_in, const int* in_sizes, int n_in,
                              void* d_out, int out_size)
{
    const float* input  = (const float*)d_in[0];
    const float* w_first= (const float*)d_in[1];
    const float* conv_a = (const float*)d_in[2];
    const float* conv_b = (const float*)d_in[3];
    const float* lin_m  = (const float*)d_in[4];
    const float* w11    = (const float*)d_in[5];
    const float* w_out  = (const float*)d_in[6];
    const float* filt_d = (const float*)d_in[7];
    const float* filt_r = (const float*)d_in[8];
    float* out = (float*)d_out;

    float *xa, *xb, *y1, *y2;
    cudaGetSymbolAddress((void**)&xa, g_xa);
    cudaGetSymbolAddress((void**)&xb, g_xb);
    cudaGetSymbolAddress((void**)&y1, g_y1);
    cudaGetSymbolAddress((void**)&y2, g_y2);

    int l = 16434;
    {
        dim3 g((l + 127) / 128, B_);
        k_first<<<g, 128>>>(input, w_first, xa, l);
    }

    float* cur = xa;
    float* alt = xb;
    for (int i = 0; i < NB_; i++) {
        int l1 = l - 2;
        int l2 = l - 4;
        int lo = l - 12;

        dim3 ga((l1 + NTC - 1) / NTC, B_);
        k_conv5<true><<<ga, 128>>>(cur, conv_a + i * CH_ * CH_ * 3, y1, l);

        dim3 gb((l2 + NTC - 1) / NTC, B_);
        k_conv5<false><<<gb, 128>>>(y1, conv_b + i * CH_ * CH_ * 3, y2, l1);

        dim3 gl((lo + NTO - 1) / NTO, B_);
        k_legrec<<<gl, 256>>>(cur, lin_m + i * CH_ * MM_ * MM_,
                              filt_d, filt_r, y2, alt, l, lo);

        float* tmp = cur; cur = alt; alt = tmp;
        l = lo;
    }

    dim3 gf((LIN_ / 2 + 127) / 128, B_);
    k_final<<<gf, 128>>>(cur, w11, w_out, out, l);
}

// round 5
// speedup vs baseline: 1.3991x; 1.3991x over previous
#include <cuda_runtime.h>
#include <math.h>

#define B_    32
#define INC_  10
#define LIN_  16384
#define CH_   20
#define NPOLY 12
#define MM_   6
#define NB_   4
// lengths: l0=16434, each block shrinks by 12 -> 16422,16410,16398,16386

#define BUFN 10520000  // >= 32*20*16434

__device__ float g_xa[BUFN];
__device__ float g_xb[BUFN];
__device__ float g_y1[BUFN];
__device__ float g_y2[BUFN];

typedef unsigned long long ull;

__device__ __forceinline__ ull pk2(float lo, float hi) {
    ull r; asm("mov.b64 %0, {%1, %2};" : "=l"(r) : "f"(lo), "f"(hi)); return r;
}
__device__ __forceinline__ void upk2(ull v, float& lo, float& hi) {
    asm("mov.b64 {%0, %1}, %2;" : "=f"(lo), "=f"(hi) : "l"(v));
}
__device__ __forceinline__ ull fma2(ull a, ull b, ull c) {
    ull d; asm("fma.rn.f32x2 %0, %1, %2, %3;" : "=l"(d) : "l"(a), "l"(b), "l"(c));
    return d;
}

// Branchless gelu: Abramowitz-Stegun 7.1.26 erf approx (|abs err| < 1.5e-7)
__device__ __forceinline__ float gelu_f(float x) {
    float z = 0.7071067811865476f * x;
    float s = fabsf(z);
    float t = __fdividef(1.0f, fmaf(0.3275911f, s, 1.0f));
    float p = fmaf(fmaf(fmaf(fmaf(1.061405429f, t, -1.453152027f),
                             t, 1.421413741f), t, -0.284496736f), t, 0.254829592f) * t;
    float e = __expf(-s * s);
    float er = fmaf(-p, e, 1.0f);
    er = copysignf(er, z);
    return 0.5f * x * (1.0f + er);
}

// ---------------------------------------------------------------------------
// First conv: input (B,10,16384) wrap-padded (25,27), conv3 -> (B,20,16434)
// ---------------------------------------------------------------------------
__global__ void __launch_bounds__(128) k_first(
    const float* __restrict__ in, const float* __restrict__ w,
    float* __restrict__ out, int lout)
{
    __shared__ float sw[CH_ * INC_ * 3];
    int tid = threadIdx.x;
    for (int i = tid; i < CH_ * INC_ * 3; i += blockDim.x) sw[i] = w[i];
    __syncthreads();

    int b = blockIdx.y;
    int t = blockIdx.x * blockDim.x + tid;
    if (t >= lout) return;

    int base = t - 25;
    int i0 = base;     if (i0 < 0) i0 += LIN_; else if (i0 >= LIN_) i0 -= LIN_;
    int i1 = base + 1; if (i1 < 0) i1 += LIN_; else if (i1 >= LIN_) i1 -= LIN_;
    int i2 = base + 2; if (i2 < 0) i2 += LIN_; else if (i2 >= LIN_) i2 -= LIN_;

    const float* inb = in + (size_t)b * INC_ * LIN_;
    float acc[CH_];
#pragma unroll
    for (int co = 0; co < CH_; co++) acc[co] = 0.f;
#pragma unroll
    for (int ci = 0; ci < INC_; ci++) {
        float v0 = inb[ci * LIN_ + i0];
        float v1 = inb[ci * LIN_ + i1];
        float v2 = inb[ci * LIN_ + i2];
#pragma unroll
        for (int co = 0; co < CH_; co++) {
            const float* wp = sw + (co * INC_ + ci) * 3;
            acc[co] = fmaf(wp[0], v0, fmaf(wp[1], v1, fmaf(wp[2], v2, acc[co])));
        }
    }
    float* ob = out + (size_t)b * CH_ * lout;
#pragma unroll
    for (int co = 0; co < CH_; co++) ob[co * lout + t] = acc[co];
}

// ---------------------------------------------------------------------------
// conv3 20->20 VALID with packed f32x2 math. Tile NTC=256 outputs.
// 4 warps x 5 co; thread handles 4 position-pairs (j = 2*lane + 64*v).
// Weights duplicated {w,w} in smem (broadcast LDS.64), hoisted per ci.
// All lengths involved are even, so pairs never split at boundaries.
// ---------------------------------------------------------------------------
#define NTC 256
#define XROW 264  // >= 258; even (8B align), 264 mod 32 = 8

template <bool DO_GELU>
__global__ void __launch_bounds__(128) k_conv_f2(
    const float* __restrict__ x, const float* __restrict__ w,
    float* __restrict__ out, int lin)
{
    __shared__ __align__(16) float xs[CH_][XROW];
    __shared__ __align__(16) float2 swd[CH_ * CH_ * 3];

    int tid = threadIdx.x;
    int b = blockIdx.y;
    int T0 = blockIdx.x * NTC;
    int lout = lin - 2;   // even

    for (int i = tid; i < CH_ * CH_ * 3; i += 128) {
        float v = w[i];
        swd[i] = make_float2(v, v);
    }
    for (int i = tid; i < CH_ * (NTC + 2); i += 128) {
        int ci = i / (NTC + 2), j = i % (NTC + 2);
        int gp = T0 + j;
        xs[ci][j] = (gp < lin) ? x[((size_t)b * CH_ + ci) * lin + gp] : 0.f;
    }
    __syncthreads();

    int wq = tid >> 5, lane = tid & 31;
    int cob = 5 * wq;

    ull zero = pk2(0.f, 0.f);
    ull a[5][4];
#pragma unroll
    for (int cc = 0; cc < 5; cc++)
#pragma unroll
        for (int v = 0; v < 4; v++) a[cc][v] = zero;

#pragma unroll
    for (int ci = 0; ci < CH_; ci++) {
        ull wr[15];
#pragma unroll
        for (int cc = 0; cc < 5; cc++)
#pragma unroll
            for (int k = 0; k < 3; k++)
                wr[cc * 3 + k] = *(const ull*)&swd[((cob + cc) * CH_ + ci) * 3 + k];
#pragma unroll
        for (int v = 0; v < 4; v++) {
            int j = 2 * lane + 64 * v;
            ull A = *(const ull*)&xs[ci][j];      // {x[j],   x[j+1]}
            ull Bv = *(const ull*)&xs[ci][j + 2]; // {x[j+2], x[j+3]}
            float a0, a1, b0, b1;
            upk2(A, a0, a1); upk2(Bv, b0, b1);
            ull M = pk2(a1, b0);                  // {x[j+1], x[j+2]}
#pragma unroll
            for (int cc = 0; cc < 5; cc++) {
                a[cc][v] = fma2(wr[cc * 3 + 0], A,  a[cc][v]);
                a[cc][v] = fma2(wr[cc * 3 + 1], M,  a[cc][v]);
                a[cc][v] = fma2(wr[cc * 3 + 2], Bv, a[cc][v]);
            }
        }
    }

#pragma unroll
    for (int v = 0; v < 4; v++) {
        int j = 2 * lane + 64 * v;
        int t = T0 + j;
        if (t < lout) {  // lout even, t even -> t+1 also valid
#pragma unroll
            for (int cc = 0; cc < 5; cc++) {
                float u0, u1;
                upk2(a[cc][v], u0, u1);
                if (DO_GELU) { u0 = gelu_f(u0); u1 = gelu_f(u1); }
                float2* op = (float2*)&out[((size_t)b * CH_ + cob + cc) * lout + t];
                *op = make_float2(u0, u1);
            }
        }
    }
}

// ---------------------------------------------------------------------------
// Legendre decomposition + cross-channel block-diag mixing (R2 version, 62us).
// Flat mode-major axis: q = mi*20 + ci.
//   v[q,t] = sum_k (fd[mi,k]*0.5) * x[b, ci, 6t+k]
//   u[p,t] = sum_i lm[p/6, p%6, i] * v[6*(p/6)+i, t]
// Output layout: Lg[((b*6 + mo)*20 + co)*ll + t] with p = mo*20 + co.
// ---------------------------------------------------------------------------
#define TB_ 32
__global__ void __launch_bounds__(640) k_legmix(
    const float* __restrict__ x, const float* __restrict__ lm_g,
    const float* __restrict__ fd, float* __restrict__ Lg, int lin, int ll)
{
    __shared__ float xs[CH_][TB_ * 6 + 6];   // 20 x 198 (198 mod 32 = 6)
    __shared__ float fd2[MM_ * NPOLY];
    __shared__ float lm[CH_ * MM_ * MM_];

    int b = blockIdx.y;
    int T0 = blockIdx.x * TB_;
    int tid = threadIdx.y * TB_ + threadIdx.x;

    for (int i = tid; i < MM_ * NPOLY; i += 640) fd2[i] = 0.5f * fd[i];
    for (int i = tid; i < CH_ * MM_ * MM_; i += 640) lm[i] = lm_g[i];
    for (int i = tid; i < CH_ * (TB_ * 6 + 6); i += 640) {
        int ci = i / (TB_ * 6 + 6);
        int j  = i % (TB_ * 6 + 6);
        int pos = 6 * T0 + j;
        xs[ci][j] = (pos < lin) ? x[((size_t)b * CH_ + ci) * lin + pos] : 0.f;
    }
    __syncthreads();

    int tloc = threadIdx.x;
    int g = threadIdx.y;
    int t = T0 + tloc;
    if (t >= ll) return;

    float v[MM_];
#pragma unroll
    for (int i = 0; i < MM_; i++) {
        int q  = 6 * g + i;
        int mi = q / CH_;
        int ci = q % CH_;
        float s = 0.f;
#pragma unroll
        for (int k = 0; k < NPOLY; k++)
            s = fmaf(fd2[mi * NPOLY + k], xs[ci][6 * tloc + k], s);
        v[i] = s;
    }
#pragma unroll
    for (int o = 0; o < MM_; o++) {
        float s = 0.f;
#pragma unroll
        for (int i = 0; i < MM_; i++)
            s = fmaf(lm[(g * MM_ + o) * MM_ + i], v[i], s);
        int p  = 6 * g + o;
        int mo = p / CH_;
        int co = p % CH_;
        Lg[(((size_t)b * MM_ + mo) * CH_ + co) * ll + t] = s;
    }
}

// ---------------------------------------------------------------------------
// Overlap-add reconstruction + residual add + gelu (R2 version).
// ---------------------------------------------------------------------------
__global__ void __launch_bounds__(128) k_recon(
    const float* __restrict__ Lg, const float* __restrict__ fr,
    const float* __restrict__ y2, float* __restrict__ out, int ll, int lout)
{
    __shared__ float sfr[MM_ * NPOLY];
    int tid = threadIdx.x;
    if (tid < MM_ * NPOLY) sfr[tid] = fr[tid];
    __syncthreads();

    int bc = blockIdx.y;
    int b = bc / CH_, co = bc % CH_;
    int t = blockIdx.x * blockDim.x + tid;
    if (t >= lout) return;

    int p = t + 6;
    int t0 = p / 6;
    int k0 = p - 6 * t0;

    const float* Lo = Lg + (((size_t)b * MM_) * CH_ + co) * ll;
    size_t mstride = (size_t)CH_ * ll;
    float s = 0.f;
#pragma unroll
    for (int m = 0; m < MM_; m++) {
        s = fmaf(Lo[m * mstride + t0],     sfr[m * NPOLY + k0],     s);
        s = fmaf(Lo[m * mstride + t0 - 1], sfr[m * NPOLY + k0 + 6], s);
    }
    int liny2 = lout + 8;
    float val = s + y2[(size_t)bc * liny2 + t + 4];
    out[(size_t)bc * lout + t] = gelu_f(val);
}

// ---------------------------------------------------------------------------
// Final 20->128(gelu)->1 with f32x2, VT=4 (two pairs per thread).
// ---------------------------------------------------------------------------
__global__ void __launch_bounds__(128) k_final_f2(
    const float* __restrict__ x, const float* __restrict__ w11,
    const float* __restrict__ w_out, float* __restrict__ out, int lin)
{
    __shared__ __align__(16) float2 swd[128 * CH_];  // duplicated {w,w}
    __shared__ float so[128];
    int tid = threadIdx.x;
    for (int i = tid; i < 128 * CH_; i += 128) {
        float v = w11[i];
        swd[i] = make_float2(v, v);
    }
    if (tid < 128) so[tid] = w_out[tid];
    __syncthreads();

    int b = blockIdx.y;
    int t0 = (blockIdx.x * 128 + tid) * 4;
    if (t0 >= LIN_) return;

    const float* xb = x + (size_t)b * CH_ * lin + t0;
    ull xv01[CH_], xv23[CH_];
#pragma unroll
    for (int c = 0; c < CH_; c++) {
        const float* xp = xb + c * lin;
        xv01[c] = pk2(xp[0], xp[1]);
        xv23[c] = pk2(xp[2], xp[3]);
    }

    ull zero = pk2(0.f, 0.f);
    ull acc01 = zero, acc23 = zero;
#pragma unroll 2
    for (int o = 0; o < 128; o++) {
        ull h01 = zero, h23 = zero;
#pragma unroll
        for (int c = 0; c < CH_; c++) {
            ull wv = *(const ull*)&swd[o * CH_ + c];
            h01 = fma2(wv, xv01[c], h01);
            h23 = fma2(wv, xv23[c], h23);
        }
        float h0, h1, h2, h3;
        upk2(h01, h0, h1); upk2(h23, h2, h3);
        float ov = so[o];
        ull ov2 = pk2(ov, ov);
        acc01 = fma2(ov2, pk2(gelu_f(h0), gelu_f(h1)), acc01);
        acc23 = fma2(ov2, pk2(gelu_f(h2), gelu_f(h3)), acc23);
    }
    float r0, r1, r2, r3;
    upk2(acc01, r0, r1); upk2(acc23, r2, r3);
    float4* op = (float4*)&out[(size_t)b * LIN_ + t0];
    *op = make_float4(r0, r1, r2, r3);
}

// ---------------------------------------------------------------------------
extern "C" void kernel_launch(void* const* d_in, const int* in_sizes, int n_in,
                              void* d_out, int out_size)
{
    const float* input  = (const float*)d_in[0];
    const float* w_first= (const float*)d_in[1];
    const float* conv_a = (const float*)d_in[2];
    const float* conv_b = (const float*)d_in[3];
    const float* lin_m  = (const float*)d_in[4];
    const float* w11    = (const float*)d_in[5];
    const float* w_out  = (const float*)d_in[6];
    const float* filt_d = (const float*)d_in[7];
    const float* filt_r = (const float*)d_in[8];
    float* out = (float*)d_out;

    float *xa, *xb, *y1, *y2;
    cudaGetSymbolAddress((void**)&xa, g_xa);
    cudaGetSymbolAddress((void**)&xb, g_xb);
    cudaGetSymbolAddress((void**)&y1, g_y1);
    cudaGetSymbolAddress((void**)&y2, g_y2);
    float* Lg = y1;  // Lg (32*120*ll ~ 10.5M) reuses y1 after conv_a consumed;
                     // but conv_b reads y1 -> use a separate buffer: g_y1 for y1,
                     // Lg goes into g_xa's sibling... (see below: Lg uses spare)
    // We need 5 live buffers max: cur, alt, y1, y2, Lg. Use static layout:
    // cur/alt ping-pong on xa/xb; y1, y2 fixed; Lg shares with nothing live.
    // Lg is written by k_legmix (reads cur) and read by k_recon (writes alt).
    // y1 is dead after conv_b, so Lg can reuse y1? k_legmix runs AFTER conv_b
    // in stream order, so y1 is indeed dead. Safe.

    int l = 16434;
    {
        dim3 g((l + 127) / 128, B_);
        k_first<<<g, 128>>>(input, w_first, xa, l);
    }

    float* cur = xa;
    float* alt = xb;
    for (int i = 0; i < NB_; i++) {
        int l1 = l - 2;
        int l2 = l - 4;
        int ll = l / 6 - 1;
        int lo = l - 12;

        dim3 ga((l1 + NTC - 1) / NTC, B_);
        k_conv_f2<true><<<ga, 128>>>(cur, conv_a + i * CH_ * CH_ * 3, y1, l);

        dim3 gb((l2 + NTC - 1) / NTC, B_);
        k_conv_f2<false><<<gb, 128>>>(y1, conv_b + i * CH_ * CH_ * 3, y2, l1);

        dim3 gl((ll + TB_ - 1) / TB_, B_);
        k_legmix<<<gl, dim3(TB_, CH_)>>>(cur, lin_m + i * CH_ * MM_ * MM_,
                                         filt_d, Lg, l, ll);

        dim3 gr((lo + 127) / 128, B_ * CH_);
        k_recon<<<gr, 128>>>(Lg, filt_r, y2, alt, ll, lo);

        float* tmp = cur; cur = alt; alt = tmp;
        l = lo;
    }

    dim3 gf((LIN_ / 4 + 127) / 128, B_);
    k_final_f2<<<gf, 128>>>(cur, w11, w_out, out, l);
}